// round 15
// baseline (speedup 1.0000x reference)
#include <cuda_runtime.h>
#include <cfloat>

#define HW   (512*512)
#define W    512
#define NCH  48            // 16 batches * 3 channels
#define FW   23
#define PAD  11

#define PB   8192          // pct histogram bins: i=(int)(res*256)+4096, res in (-16,16)
#define CAP  16384         // median candidate capacity per channel
#define SEG  8             // med_count blocks per channel
// median fast-path candidate window in value space: [-10/512, +10/512)
#define T_LO (-10.0f/512.0f)
#define T_HI ( 10.0f/512.0f)

// fused conv: 64-col band per block, 4 row-quadrant streams of 64 threads
#define BAND  64
#define NSTR  4
#define QROWS 128                  // output rows per stream
#define QIN   (QROWS + 2*PAD)      // 150 input rows per stream
#define CITERS 38                  // ceil((QIN)/4) covering emit tail
// smem (floats): xrow 4*4*86 + hring 4*32*64 + xpring 4*16*64, then u32 hist
#define SM_XROW   0
#define SM_HRING  (NSTR*4*86)
#define SM_XPRING (SM_HRING + NSTR*32*64)
#define SM_HIST   (SM_XPRING + NSTR*16*64)
#define CONV_SMEM ((SM_HIST + PB/2) * 4)

// scratch (no cudaMalloc allowed; zero-initialized at load, kernels restore zeros)
__device__ float    g_res[(size_t)NCH * HW];
__device__ unsigned g_phist[NCH * PB];
__device__ float    g_cand[NCH * CAP];
__device__ int      g_ccount[NCH];
__device__ int      g_below[NCH];
__device__ int      g_mdone[NCH];
__device__ float    g_med[NCH];
__device__ float    g_lo[NCH];
__device__ float    g_hi[NCH];
__device__ float    g_k1[FW];

// ---------------------------------------------------------------------------
// block-wide exclusive scan over NT threads (shuffle-based)
// ---------------------------------------------------------------------------
template <int NT>
__device__ __forceinline__ unsigned block_excl_scan(unsigned val) {
    __shared__ unsigned warpsum[NT / 32];
    const unsigned lane = threadIdx.x & 31, wid = threadIdx.x >> 5;
    unsigned s = val;
    #pragma unroll
    for (int o = 1; o < 32; o <<= 1) {
        unsigned t = __shfl_up_sync(0xFFFFFFFFu, s, o);
        if (lane >= o) s += t;
    }
    if (lane == 31) warpsum[wid] = s;
    __syncthreads();
    if (wid == 0) {
        unsigned w = (lane < NT / 32) ? warpsum[lane] : 0u;
        #pragma unroll
        for (int o = 1; o < 32; o <<= 1) {
            unsigned t = __shfl_up_sync(0xFFFFFFFFu, w, o);
            if (lane >= o) w += t;
        }
        if (lane < NT / 32) warpsum[lane] = w;
    }
    __syncthreads();
    unsigned wexcl = wid ? warpsum[wid - 1] : 0u;
    return wexcl + s - val;
}

__device__ __forceinline__ int med_bin(float v) {   // for fallback only
    int b = (int)floorf(fmaf(v, 512.0f, 4096.0f));
    return b < 0 ? 0 : (b > 8191 ? 8191 : b);
}

// ---------------------------------------------------------------------------
// exact median selection, 512 threads (runs in the last med_count block/channel)
// ---------------------------------------------------------------------------
__device__ void med_select_block(int ch, const float* __restrict__ x) {
    __shared__ unsigned fh[8192];                     // 32 KB
    __shared__ float s_red[16];
    __shared__ float s_mn, s_mx;
    __shared__ int s_fb, s_r2, s_n, s_k2, s_cnt, s_selbin;
    __shared__ float mem[512];
    __shared__ int mcount;

    const int tid = threadIdx.x;
    const int k = (HW - 1) / 2;
    int below = g_below[ch];
    int cnt   = g_ccount[ch];
    __syncthreads();
    if (tid == 0) {
        g_below[ch] = 0; g_ccount[ch] = 0; g_mdone[ch] = 0;   // restore for replay
        s_cnt = 0;
    }
    const bool fast = (below <= k) && (k < below + cnt) && (cnt <= CAP);

    if (fast) {
        if (tid == 0) { s_n = cnt; s_k2 = k - below; }
        __syncthreads();
    } else {
        // exact fallback (rare): coarse hist over channel, then collect
        for (int i = tid; i < 8192; i += 512) fh[i] = 0;
        __syncthreads();
        const float4* p = (const float4*)(x + (size_t)ch * HW);
        for (int i = tid; i < HW / 4; i += 512) {
            float4 v = p[i];
            atomicAdd(&fh[med_bin(v.x)], 1u);
            atomicAdd(&fh[med_bin(v.y)], 1u);
            atomicAdd(&fh[med_bin(v.z)], 1u);
            atomicAdd(&fh[med_bin(v.w)], 1u);
        }
        __syncthreads();
        unsigned loc[16];
        unsigned s = 0;
        #pragma unroll
        for (int j = 0; j < 16; j++) { loc[j] = fh[tid * 16 + j]; s += loc[j]; }
        unsigned pref = block_excl_scan<512>(s);
        if (pref <= (unsigned)k && (unsigned)k < pref + s) {
            unsigned cum = pref;
            #pragma unroll
            for (int j = 0; j < 16; j++) {
                unsigned c = loc[j];
                if (cum + c > (unsigned)k) { s_selbin = tid * 16 + j; s_k2 = (int)(k - cum); break; }
                cum += c;
            }
        }
        __syncthreads();
        const int sb = s_selbin;
        for (int i = tid; i < HW / 4; i += 512) {
            float4 v = p[i];
            float vv[4] = { v.x, v.y, v.z, v.w };
            #pragma unroll
            for (int j = 0; j < 4; j++) {
                if (med_bin(vv[j]) == sb) {
                    int pp = atomicAdd(&s_cnt, 1);
                    if (pp < CAP) g_cand[ch * CAP + pp] = vv[j];
                }
            }
        }
        __syncthreads();
        if (tid == 0) s_n = s_cnt < CAP ? s_cnt : CAP;
        __syncthreads();
    }

    const int n = s_n, k2 = s_k2;
    const float* c = g_cand + ch * CAP;

    // min/max reduce over candidates
    float mn = FLT_MAX, mx = -FLT_MAX;
    for (int i = tid; i < n; i += 512) {
        float v = c[i];
        mn = fminf(mn, v); mx = fmaxf(mx, v);
    }
    for (int o = 16; o; o >>= 1) {
        mn = fminf(mn, __shfl_down_sync(0xFFFFFFFFu, mn, o));
        mx = fmaxf(mx, __shfl_down_sync(0xFFFFFFFFu, mx, o));
    }
    if ((tid & 31) == 0) s_red[tid >> 5] = mn;
    __syncthreads();
    if (tid < 16) {
        float v = s_red[tid];
        for (int o = 8; o; o >>= 1) v = fminf(v, __shfl_down_sync(0xFFFFu, v, o));
        if (tid == 0) s_mn = v;
    }
    __syncthreads();
    if ((tid & 31) == 0) s_red[tid >> 5] = mx;
    __syncthreads();
    if (tid < 16) {
        float v = s_red[tid];
        for (int o = 8; o; o >>= 1) v = fmaxf(v, __shfl_down_sync(0xFFFFu, v, o));
        if (tid == 0) s_mx = v;
    }
    __syncthreads();
    const float mnv = s_mn, mxv = s_mx;
    if (mnv == mxv) { if (tid == 0) g_med[ch] = mnv + 0.2f; return; }

    // fine histogram over candidates
    for (int i = tid; i < 8192; i += 512) fh[i] = 0;
    __syncthreads();
    const float scale = 8192.0f / (mxv - mnv);
    for (int i = tid; i < n; i += 512) {
        int b = (int)((c[i] - mnv) * scale);
        b = b < 0 ? 0 : (b > 8191 ? 8191 : b);
        atomicAdd(&fh[b], 1u);
    }
    __syncthreads();
    unsigned loc[16];
    unsigned s = 0;
    #pragma unroll
    for (int j = 0; j < 16; j++) { loc[j] = fh[tid * 16 + j]; s += loc[j]; }
    unsigned pref = block_excl_scan<512>(s);
    if (pref <= (unsigned)k2 && (unsigned)k2 < pref + s) {
        unsigned cum = pref;
        #pragma unroll
        for (int j = 0; j < 16; j++) {
            unsigned cc = loc[j];
            if (cum + cc > (unsigned)k2) { s_fb = tid * 16 + j; s_r2 = (int)(k2 - cum); break; }
            cum += cc;
        }
    }
    if (tid == 0) mcount = 0;
    __syncthreads();
    const int fb = s_fb, r2 = s_r2;
    for (int i = tid; i < n; i += 512) {
        int b = (int)((c[i] - mnv) * scale);
        b = b < 0 ? 0 : (b > 8191 ? 8191 : b);
        if (b == fb) {
            int pp = atomicAdd(&mcount, 1);
            if (pp < 512) mem[pp] = c[i];
        }
    }
    __syncthreads();
    int m = mcount < 512 ? mcount : 512;
    for (int i = tid; i < m; i += 512) {
        float vi = mem[i];
        int r = 0;
        for (int j = 0; j < m; j++) {
            float vj = mem[j];
            r += (vj < vi) || (vj == vi && j < i);
        }
        if (r == r2) g_med[ch] = vi + 0.2f;
    }
}

// ---------------------------------------------------------------------------
// launch #1: below-count + window-candidate collect + k1; last block per
// channel runs exact median selection inline.
// ---------------------------------------------------------------------------
__global__ __launch_bounds__(512)
void med_count(const float* __restrict__ x, const float* __restrict__ kern) {
    __shared__ int s_done;
    const int ch = blockIdx.x / SEG, seg = blockIdx.x % SEG;
    const int tid = threadIdx.x;
    if (blockIdx.x == 0 && tid < FW) {
        float s = 0.0f;
        for (int j = 0; j < FW; j++) s += kern[tid * FW + j];
        g_k1[tid] = s;
    }
    const float4* p = (const float4*)(x + (size_t)ch * HW) + (size_t)seg * (HW / 4 / SEG);
    int below = 0;
    for (int i = tid; i < HW / 4 / SEG; i += 512) {
        float4 v = p[i];
        float vv[4] = { v.x, v.y, v.z, v.w };
        #pragma unroll
        for (int j = 0; j < 4; j++) {
            float f = vv[j];
            below += (f < T_LO);
            if (f >= T_LO && f < T_HI) {
                int pp = atomicAdd(&g_ccount[ch], 1);
                if (pp < CAP) g_cand[ch * CAP + pp] = f;
            }
        }
    }
    for (int o = 16; o; o >>= 1) below += __shfl_down_sync(0xFFFFFFFFu, below, o);
    if ((tid & 31) == 0 && below) atomicAdd(&g_below[ch], below);

    // last block of this channel performs the selection
    __syncthreads();
    __threadfence();
    if (tid == 0) s_done = atomicAdd(&g_mdone[ch], 1);
    __syncthreads();
    if (s_done == SEG - 1) {
        __threadfence();
        med_select_block(ch, x);
    }
}

// ---------------------------------------------------------------------------
// launch #2: FUSED separable conv (rolling ring buffers, no g_tmp) + res +
// fused packed-u16 pct histogram.
// Block = 64-col band x full height, as 4 independent 128-row streams of 64
// threads. Per 4-row iteration: load xp -> h-conv -> ring -> v-conv/emit.
// ---------------------------------------------------------------------------
__global__ __launch_bounds__(256)
void conv_fused(const float* __restrict__ x, const float* __restrict__ mask) {
    extern __shared__ float sm[];
    float*    xrow   = sm + SM_XROW;     // [NSTR][4][86]
    float*    hring  = sm + SM_HRING;    // [NSTR][32][64]
    float*    xpring = sm + SM_XPRING;   // [NSTR][16][64]
    unsigned* s_h    = (unsigned*)(sm + SM_HIST);   // PB/2 packed
    __shared__ float s_k[FW];

    const int tid = threadIdx.x;
    const int ch = blockIdx.y;
    const int nb = ch / 3;
    const int bx = blockIdx.x * BAND;
    const int s  = tid >> 6;             // stream (row quadrant)
    const int t  = tid & 63;

    if (tid < FW) s_k[tid] = g_k1[tid];
    for (int i = tid; i < PB / 2; i += 256) s_h[i] = 0;

    const float* xc = x + (size_t)ch * HW;
    const float* mc = mask + (size_t)nb * HW;
    const float med = g_med[ch];
    const int rowbase = s * QROWS - PAD; // input row of local hy=0

    float* xr = xrow   + s * (4 * 86);
    float* hr = hring  + s * (32 * 64);
    float* xq = xpring + s * (16 * 64);

    __syncthreads();

    for (int i = 0; i < CITERS; i++) {
        const int hy0 = 4 * i;

        // phase 1: load xp rows hy0..hy0+3 (clamped), stash centers in xpring
        for (int j = t; j < 4 * 86; j += 64) {
            int r = j / 86;
            int c = j - r * 86;
            int hy = hy0 + r;
            if (hy < QIN) {
                int ri = min(max(rowbase + hy, 0), 511);
                int gc = min(max(bx - PAD + c, 0), 511);
                float xv = xc[ri * W + gc];
                float mv = mc[ri * W + gc];
                float v = mv * xv + (1.0f - mv) * med;
                xr[r * 86 + c] = v;
                int l = hy - PAD;
                if (l >= 0 && l < QROWS && c >= PAD && c < PAD + BAND)
                    xq[(l & 15) * 64 + (c - PAD)] = v;
            }
        }
        __syncthreads();

        // phase 2: h-conv, 4 rows x 16 groups of 4 outputs (1 task/thread)
        {
            int r = t >> 4, g = t & 15;
            int hy = hy0 + r;
            if (hy < QIN) {
                const float* row = xr + r * 86 + g * 4;
                float v[26];
                #pragma unroll
                for (int q = 0; q < 26; q++) v[q] = row[q];
                float* hout = hr + (hy & 31) * 64 + g * 4;
                #pragma unroll
                for (int m = 0; m < 4; m++) {
                    float a = 0.0f;
                    #pragma unroll
                    for (int tt = 0; tt < FW; tt++) a = fmaf(v[m + tt], s_k[tt], a);
                    hout[m] = a;
                }
            }
        }
        __syncthreads();

        // phase 3: v-conv + res + hist; emit local rows l0..l0+3, column t
        {
            const int l0 = 4 * i - 2 * PAD;
            #pragma unroll
            for (int m = 0; m < 4; m++) {
                int l = l0 + m;
                if (l >= 0 && l < QROWS) {
                    float a = 0.0f;
                    #pragma unroll
                    for (int tt = 0; tt < FW; tt++)
                        a = fmaf(hr[((l + tt) & 31) * 64 + t], s_k[tt], a);
                    float xpv = xq[(l & 15) * 64 + t];
                    float rv = 4.0f * (xpv - a);
                    int y = s * QROWS + l;
                    g_res[(size_t)ch * HW + (size_t)y * W + bx + t] = rv;
                    int b = (int)(rv * 256.0f) + PB / 2;
                    b = b < 0 ? 0 : (b > PB - 1 ? PB - 1 : b);
                    atomicAdd(&s_h[b >> 1], 1u << ((b & 1) * 16));
                }
            }
        }
        __syncthreads();   // protect xpring/hring reads from next iter's writes
    }

    // flush fused percentile histogram (unpack u16 pairs)
    unsigned* gh = g_phist + ch * PB;
    for (int i = tid; i < PB / 2; i += 256) {
        unsigned w2 = s_h[i];
        unsigned lo = w2 & 0xFFFFu, hi = w2 >> 16;
        if (lo) atomicAdd(&gh[2 * i], lo);
        if (hi) atomicAdd(&gh[2 * i + 1], hi);
    }
}

// ---------------------------------------------------------------------------
// launch #3: extract lo/hi percentiles, restore hist to zero
// ---------------------------------------------------------------------------
__global__ __launch_bounds__(1024)
void pct_scan() {
    const int ch = blockIdx.x, tid = threadIdx.x;
    unsigned* h = g_phist + ch * PB;
    unsigned loc[PB / 1024];
    unsigned s = 0;
    #pragma unroll
    for (int j = 0; j < PB / 1024; j++) { loc[j] = h[tid * (PB / 1024) + j]; s += loc[j]; }
    unsigned pref = block_excl_scan<1024>(s);

    const double n1 = (double)(HW - 1);
    #pragma unroll
    for (int rsel = 0; rsel < 2; rsel++) {
        double pos = n1 * (rsel ? 0.97 : 0.03);
        unsigned k = (unsigned)pos;
        float fr = (float)(pos - (double)k);
        if (pref <= k && k < pref + s) {
            unsigned cum = pref;
            #pragma unroll
            for (int j = 0; j < PB / 1024; j++) {
                unsigned c = loc[j];
                int b = tid * (PB / 1024) + j;
                if (cum + c > k) {
                    float v = (float)(b - PB / 2) * (1.0f / 256.0f);
                    float v1 = v;
                    if (k + 1 >= cum + c) {               // next value in a later bin
                        int b2 = b + 1;
                        while (b2 < PB && h[b2] == 0) b2++;
                        if (b2 < PB) v1 = (float)(b2 - PB / 2) * (1.0f / 256.0f);
                    }
                    float out = v + fr * (v1 - v);
                    if (rsel) g_hi[ch] = out; else g_lo[ch] = out;
                    break;
                }
                cum += c;
            }
        }
    }
    __syncthreads();
    // restore histogram to zero for the next replay
    #pragma unroll
    for (int j = 0; j < PB / 1024; j++) h[tid * (PB / 1024) + j] = 0u;
}

// ---------------------------------------------------------------------------
// launch #4: normalize + mask
// ---------------------------------------------------------------------------
__global__ __launch_bounds__(512)
void final_kernel(const float* __restrict__ mask, float* __restrict__ out) {
    const int ch = blockIdx.y;
    const int nb = ch / 3;
    const int i = blockIdx.x * blockDim.x + threadIdx.x;
    const float lo = g_lo[ch], hi = g_hi[ch];
    const float inv = 1.0f / (hi - lo);
    float4 r = ((const float4*)(g_res + (size_t)ch * HW))[i];
    float4 m = ((const float4*)(mask + (size_t)nb * HW))[i];
    float4 o;
    o.x = (r.x - lo) * inv * m.x;
    o.y = (r.y - lo) * inv * m.y;
    o.z = (r.z - lo) * inv * m.z;
    o.w = (r.w - lo) * inv * m.w;
    ((float4*)out)[(size_t)ch * (HW / 4) + i] = o;
}

// ---------------------------------------------------------------------------
extern "C" void kernel_launch(void* const* d_in, const int* in_sizes, int n_in,
                              void* d_out, int out_size) {
    const float* x    = (const float*)d_in[0];
    const float* mask = (const float*)d_in[1];
    const float* kern = (const float*)d_in[2];
    float* out = (float*)d_out;

    cudaFuncSetAttribute(conv_fused, cudaFuncAttributeMaxDynamicSharedMemorySize, CONV_SMEM);

    med_count<<<NCH * SEG, 512>>>(x, kern);
    conv_fused<<<dim3(W / BAND, NCH), 256, CONV_SMEM>>>(x, mask);
    pct_scan<<<NCH, 1024>>>();
    final_kernel<<<dim3(HW / 4 / 512, NCH), 512>>>(mask, out);
}

// round 16
// speedup vs baseline: 1.2598x; 1.2598x over previous
#include <cuda_runtime.h>
#include <cfloat>

#define HW   (512*512)
#define W    512
#define NCH  48            // 16 batches * 3 channels
#define FW   23
#define PAD  11

#define PB   8192          // pct histogram bins: i=(int)(res*256)+4096, res in (-16,16)
#define CAP  16384         // median candidate capacity per channel
#define SEG  8             // data-pass blocks per channel
// median fast-path candidate window in value space: [-10/512, +10/512)
#define T_LO (-10.0f/512.0f)
#define T_HI ( 10.0f/512.0f)

// hconv: 4 full rows per block, 256 threads (1 sliding group of 8 per thread)
#define HROWS 4
#define HROWW (W + 2*PAD)          // 534
// vconv: 64x128 output tile, 512 threads (2 sliding groups of 8 per thread)
#define VTX 64
#define VTY 128
#define VSH (VTY + 2*PAD)          // 150 rows of g_tmp
#define VCONV_SMEM ((VSH*VTX + PB/2) * 4)   // 37.5 KB tile + 16 KB packed hist

// scratch (no cudaMalloc allowed; zero-initialized at load, kernels restore zeros)
// g_res lifecycle per run: hconv writes xp -> vconv reads xp / overwrites res
// (same address, per-element read-before-write) -> final reads res.
__device__ float    g_res[(size_t)NCH * HW];
__device__ float    g_tmp[(size_t)NCH * HW];
__device__ unsigned g_phist[NCH * PB];
__device__ float    g_cand[NCH * CAP];
__device__ int      g_ccount[NCH];
__device__ int      g_below[NCH];
__device__ float    g_med[NCH];
__device__ float    g_lo[NCH];
__device__ float    g_hi[NCH];
__device__ float    g_k1[FW];

// ---------------------------------------------------------------------------
// block-wide exclusive scan over 1024 threads (shuffle-based)
// ---------------------------------------------------------------------------
__device__ __forceinline__ unsigned block_excl_scan_1024(unsigned val) {
    __shared__ unsigned warpsum[32];
    const unsigned lane = threadIdx.x & 31, wid = threadIdx.x >> 5;
    unsigned s = val;
    #pragma unroll
    for (int o = 1; o < 32; o <<= 1) {
        unsigned t = __shfl_up_sync(0xFFFFFFFFu, s, o);
        if (lane >= o) s += t;
    }
    if (lane == 31) warpsum[wid] = s;
    __syncthreads();
    if (wid == 0) {
        unsigned w = warpsum[lane];
        #pragma unroll
        for (int o = 1; o < 32; o <<= 1) {
            unsigned t = __shfl_up_sync(0xFFFFFFFFu, w, o);
            if (lane >= o) w += t;
        }
        warpsum[lane] = w;
    }
    __syncthreads();
    unsigned wexcl = wid ? warpsum[wid - 1] : 0u;
    return wexcl + s - val;
}

__device__ __forceinline__ int med_bin(float v) {   // for fallback only
    int b = (int)floorf(fmaf(v, 512.0f, 4096.0f));
    return b < 0 ? 0 : (b > 8191 ? 8191 : b);
}

// ---------------------------------------------------------------------------
// launch #1: count values below window + collect window candidates + k1 prep
// ---------------------------------------------------------------------------
__global__ __launch_bounds__(512)
void med_count(const float* __restrict__ x, const float* __restrict__ kern) {
    const int ch = blockIdx.x / SEG, seg = blockIdx.x % SEG;
    const int tid = threadIdx.x;
    if (blockIdx.x == 0 && tid < FW) {
        float s = 0.0f;
        for (int j = 0; j < FW; j++) s += kern[tid * FW + j];
        g_k1[tid] = s;
    }
    const float4* p = (const float4*)(x + (size_t)ch * HW) + (size_t)seg * (HW / 4 / SEG);
    int below = 0;
    for (int i = tid; i < HW / 4 / SEG; i += 512) {
        float4 v = p[i];
        float vv[4] = { v.x, v.y, v.z, v.w };
        #pragma unroll
        for (int j = 0; j < 4; j++) {
            float f = vv[j];
            below += (f < T_LO);
            if (f >= T_LO && f < T_HI) {
                int pp = atomicAdd(&g_ccount[ch], 1);
                if (pp < CAP) g_cand[ch * CAP + pp] = f;
            }
        }
    }
    for (int o = 16; o; o >>= 1) below += __shfl_down_sync(0xFFFFFFFFu, below, o);
    if ((tid & 31) == 0 && below) atomicAdd(&g_below[ch], below);
}

// ---------------------------------------------------------------------------
// launch #2: exact median selection (fast path via window; exact fallback)
// ---------------------------------------------------------------------------
__global__ __launch_bounds__(1024)
void med_sel(const float* __restrict__ x) {
    const int ch = blockIdx.x, tid = threadIdx.x;
    __shared__ unsigned fh[8192];
    __shared__ float s_red[32];
    __shared__ float s_mn, s_mx;
    __shared__ int s_fb, s_r2, s_n, s_k2;
    __shared__ int s_cnt;
    __shared__ float mem[512];
    __shared__ int mcount;

    const int k = (HW - 1) / 2;
    int below = g_below[ch];
    int cnt   = g_ccount[ch];
    __syncthreads();
    if (tid == 0) {
        g_below[ch] = 0;
        g_ccount[ch] = 0;
        s_cnt = 0;
    }
    const bool fast = (below <= k) && (k < below + cnt) && (cnt <= CAP);

    if (fast) {
        if (tid == 0) { s_n = cnt; s_k2 = k - below; }
        __syncthreads();
    } else {
        for (int i = tid; i < 8192; i += 1024) fh[i] = 0;
        __syncthreads();
        const float4* p = (const float4*)(x + (size_t)ch * HW);
        for (int i = tid; i < HW / 4; i += 1024) {
            float4 v = p[i];
            atomicAdd(&fh[med_bin(v.x)], 1u);
            atomicAdd(&fh[med_bin(v.y)], 1u);
            atomicAdd(&fh[med_bin(v.z)], 1u);
            atomicAdd(&fh[med_bin(v.w)], 1u);
        }
        __syncthreads();
        unsigned loc[8];
        unsigned s = 0;
        #pragma unroll
        for (int j = 0; j < 8; j++) { loc[j] = fh[tid * 8 + j]; s += loc[j]; }
        unsigned pref = block_excl_scan_1024(s);
        __shared__ int s_selbin;
        if (pref <= (unsigned)k && (unsigned)k < pref + s) {
            unsigned cum = pref;
            #pragma unroll
            for (int j = 0; j < 8; j++) {
                unsigned c = loc[j];
                if (cum + c > (unsigned)k) { s_selbin = tid * 8 + j; s_k2 = (int)(k - cum); break; }
                cum += c;
            }
        }
        __syncthreads();
        const int sb = s_selbin;
        for (int i = tid; i < HW / 4; i += 1024) {
            float4 v = p[i];
            float vv[4] = { v.x, v.y, v.z, v.w };
            #pragma unroll
            for (int j = 0; j < 4; j++) {
                if (med_bin(vv[j]) == sb) {
                    int pp = atomicAdd(&s_cnt, 1);
                    if (pp < CAP) g_cand[ch * CAP + pp] = vv[j];
                }
            }
        }
        __syncthreads();
        if (tid == 0) s_n = s_cnt < CAP ? s_cnt : CAP;
        __syncthreads();
    }

    const int n = s_n, k2 = s_k2;
    const float* c = g_cand + ch * CAP;

    float mn = FLT_MAX, mx = -FLT_MAX;
    for (int i = tid; i < n; i += 1024) {
        float v = c[i];
        mn = fminf(mn, v); mx = fmaxf(mx, v);
    }
    for (int o = 16; o; o >>= 1) {
        mn = fminf(mn, __shfl_down_sync(0xFFFFFFFFu, mn, o));
        mx = fmaxf(mx, __shfl_down_sync(0xFFFFFFFFu, mx, o));
    }
    if ((tid & 31) == 0) s_red[tid >> 5] = mn;
    __syncthreads();
    if (tid < 32) {
        float v = s_red[tid];
        for (int o = 16; o; o >>= 1) v = fminf(v, __shfl_down_sync(0xFFFFFFFFu, v, o));
        if (tid == 0) s_mn = v;
    }
    __syncthreads();
    if ((tid & 31) == 0) s_red[tid >> 5] = mx;
    __syncthreads();
    if (tid < 32) {
        float v = s_red[tid];
        for (int o = 16; o; o >>= 1) v = fmaxf(v, __shfl_down_sync(0xFFFFFFFFu, v, o));
        if (tid == 0) s_mx = v;
    }
    __syncthreads();
    const float mnv = s_mn, mxv = s_mx;
    if (mnv == mxv) { if (tid == 0) g_med[ch] = mnv + 0.2f; return; }

    for (int i = tid; i < 8192; i += 1024) fh[i] = 0;
    __syncthreads();
    const float scale = 8192.0f / (mxv - mnv);
    for (int i = tid; i < n; i += 1024) {
        int b = (int)((c[i] - mnv) * scale);
        b = b < 0 ? 0 : (b > 8191 ? 8191 : b);
        atomicAdd(&fh[b], 1u);
    }
    __syncthreads();
    unsigned loc[8];
    unsigned s = 0;
    #pragma unroll
    for (int j = 0; j < 8; j++) { loc[j] = fh[tid * 8 + j]; s += loc[j]; }
    unsigned pref = block_excl_scan_1024(s);
    if (pref <= (unsigned)k2 && (unsigned)k2 < pref + s) {
        unsigned cum = pref;
        #pragma unroll
        for (int j = 0; j < 8; j++) {
            unsigned cc = loc[j];
            if (cum + cc > (unsigned)k2) { s_fb = tid * 8 + j; s_r2 = (int)(k2 - cum); break; }
            cum += cc;
        }
    }
    if (tid == 0) mcount = 0;
    __syncthreads();
    const int fb = s_fb, r2 = s_r2;
    for (int i = tid; i < n; i += 1024) {
        int b = (int)((c[i] - mnv) * scale);
        b = b < 0 ? 0 : (b > 8191 ? 8191 : b);
        if (b == fb) {
            int pp = atomicAdd(&mcount, 1);
            if (pp < 512) mem[pp] = c[i];
        }
    }
    __syncthreads();
    int m = mcount < 512 ? mcount : 512;
    for (int i = tid; i < m; i += 1024) {
        float vi = mem[i];
        int r = 0;
        for (int j = 0; j < m; j++) {
            float vj = mem[j];
            r += (vj < vi) || (vj == vi && j < i);
        }
        if (r == r2) g_med[ch] = vi + 0.2f;
    }
}

// ---------------------------------------------------------------------------
// launch #3: horizontal conv — 4 full rows/block, xp fused; writes h-conv to
// g_tmp AND xp to g_res (consumed in place by vconv). No div/mod in fill.
// ---------------------------------------------------------------------------
__global__ __launch_bounds__(256)
void hconv(const float* __restrict__ x, const float* __restrict__ mask) {
    __shared__ float xp[HROWS][HROWW];                // 4 x 534 floats = 8.5 KB
    __shared__ float s_k[FW];
    const int tid = threadIdx.x;
    const int ch = blockIdx.y;
    const int nb = ch / 3;
    const int row0 = blockIdx.x * HROWS;

    if (tid < FW) s_k[tid] = g_k1[tid];

    const float* xc = x + (size_t)ch * HW;
    const float* mc = mask + (size_t)nb * HW;
    const float med = g_med[ch];

    #pragma unroll
    for (int r = 0; r < HROWS; r++) {
        const float* xr = xc + (size_t)(row0 + r) * W;
        const float* mr = mc + (size_t)(row0 + r) * W;
        for (int cc = tid; cc < HROWW; cc += 256) {
            int gc = min(max(cc - PAD, 0), W - 1);
            float xv = xr[gc];
            float mv = mr[gc];
            xp[r][cc] = mv * xv + (1.0f - mv) * med;
        }
    }
    __syncthreads();

    const int r = tid >> 6, g = tid & 63;
    const float* rowp = xp[r] + g * 8;
    float w[10], acc[8];
    #pragma unroll
    for (int i = 0; i < 5; i++) {
        float2 v = *(const float2*)(rowp + 2 * i);
        w[2 * i] = v.x; w[2 * i + 1] = v.y;
    }
    #pragma unroll
    for (int m = 0; m < 8; m++) acc[m] = 0.0f;
    #pragma unroll
    for (int tp = 0; tp < 11; tp++) {
        const float k0 = s_k[2 * tp], k1v = s_k[2 * tp + 1];
        #pragma unroll
        for (int m = 0; m < 8; m++) acc[m] = fmaf(w[m], k0, acc[m]);
        #pragma unroll
        for (int m = 0; m < 8; m++) acc[m] = fmaf(w[m + 1], k1v, acc[m]);
        if (tp < 10) {
            #pragma unroll
            for (int m = 0; m < 8; m++) w[m] = w[m + 2];
            float2 v = *(const float2*)(rowp + 2 * tp + 10);
            w[8] = v.x; w[9] = v.y;
        }
    }
    const float k22 = s_k[22];
    #pragma unroll
    for (int m = 0; m < 8; m++) acc[m] = fmaf(w[m + 2], k22, acc[m]);

    const size_t base = (size_t)ch * HW + (size_t)(row0 + r) * W + g * 8;
    float4* outp = (float4*)(g_tmp + base);
    outp[0] = make_float4(acc[0], acc[1], acc[2], acc[3]);
    outp[1] = make_float4(acc[4], acc[5], acc[6], acc[7]);

    // stash xp (central values) for vconv: xp at out col c is xp[r][c+PAD]
    float4* xpo = (float4*)(g_res + base);
    const float* xs = xp[r] + g * 8 + PAD;
    xpo[0] = make_float4(xs[0], xs[1], xs[2], xs[3]);
    xpo[1] = make_float4(xs[4], xs[5], xs[6], xs[7]);
}

// ---------------------------------------------------------------------------
// launch #4: vertical conv + res (in place over xp) + fused packed-u16 pct hist
// 64x128 tile (halo 17%), 512 threads, 2 sliding groups of 8 per thread
// ---------------------------------------------------------------------------
__global__ __launch_bounds__(512)
void vconv() {
    extern __shared__ float dsm[];
    float*    st  = dsm;                              // VSH x VTX g_tmp tile
    unsigned* s_h = (unsigned*)(dsm + VSH * VTX);     // PB/2 packed hist
    __shared__ float s_k[FW];

    const int tid = threadIdx.x;
    const int ch = blockIdx.z;
    const int bx = blockIdx.x * VTX, by = blockIdx.y * VTY;

    if (tid < FW) s_k[tid] = g_k1[tid];
    for (int i = tid; i < PB / 2; i += 512) s_h[i] = 0;

    const float* tc = g_tmp + (size_t)ch * HW;
    for (int i = tid; i < VSH * VTX; i += 512) {
        int r = i >> 6, c = i & 63;
        int gy = min(max(by - PAD + r, 0), 511);
        st[r * VTX + c] = tc[gy * W + bx + c];
    }
    __syncthreads();

    // two vertical sliding-window groups of 8 outputs per thread
    const int xx = tid & 63;
    const int ybase = (tid >> 6) * 16;                // 8 slots of 16 rows
    #pragma unroll
    for (int g2 = 0; g2 < 2; g2++) {
        const int y0 = ybase + g2 * 8;
        const float* col = st + y0 * VTX + xx;
        float w[8], acc[8];
        #pragma unroll
        for (int m = 0; m < 8; m++) { w[m] = col[m * VTX]; acc[m] = 0.0f; }
        #pragma unroll
        for (int t = 0; t < FW; t++) {
            const float kt = s_k[t];
            #pragma unroll
            for (int m = 0; m < 8; m++) acc[m] = fmaf(w[m], kt, acc[m]);
            if (t < FW - 1) {
                #pragma unroll
                for (int m = 0; m < 7; m++) w[m] = w[m + 1];
                w[7] = col[(t + 8) * VTX];
            }
        }

        // read xp (stored by hconv) and overwrite with res, same address
        float* rp = g_res + (size_t)ch * HW + (size_t)(by + y0) * W + bx + xx;
        #pragma unroll
        for (int m = 0; m < 8; m++) {
            float xpv = rp[m * W];
            float rv = 4.0f * (xpv - acc[m]);
            rp[m * W] = rv;
            int b = (int)(rv * 256.0f) + PB / 2;
            b = b < 0 ? 0 : (b > PB - 1 ? PB - 1 : b);
            atomicAdd(&s_h[b >> 1], 1u << ((b & 1) * 16));
        }
    }
    __syncthreads();

    unsigned* gh = g_phist + ch * PB;
    for (int i = tid; i < PB / 2; i += 512) {
        unsigned w2 = s_h[i];
        unsigned lo = w2 & 0xFFFFu, hi = w2 >> 16;
        if (lo) atomicAdd(&gh[2 * i], lo);
        if (hi) atomicAdd(&gh[2 * i + 1], hi);
    }
}

// ---------------------------------------------------------------------------
// launch #5: extract lo/hi percentiles, restore hist to zero
// ---------------------------------------------------------------------------
__global__ __launch_bounds__(1024)
void pct_scan() {
    const int ch = blockIdx.x, tid = threadIdx.x;
    unsigned* h = g_phist + ch * PB;
    unsigned loc[PB / 1024];
    unsigned s = 0;
    #pragma unroll
    for (int j = 0; j < PB / 1024; j++) { loc[j] = h[tid * (PB / 1024) + j]; s += loc[j]; }
    unsigned pref = block_excl_scan_1024(s);

    const double n1 = (double)(HW - 1);
    #pragma unroll
    for (int rsel = 0; rsel < 2; rsel++) {
        double pos = n1 * (rsel ? 0.97 : 0.03);
        unsigned k = (unsigned)pos;
        float fr = (float)(pos - (double)k);
        if (pref <= k && k < pref + s) {
            unsigned cum = pref;
            #pragma unroll
            for (int j = 0; j < PB / 1024; j++) {
                unsigned c = loc[j];
                int b = tid * (PB / 1024) + j;
                if (cum + c > k) {
                    float v = (float)(b - PB / 2) * (1.0f / 256.0f);
                    float v1 = v;
                    if (k + 1 >= cum + c) {
                        int b2 = b + 1;
                        while (b2 < PB && h[b2] == 0) b2++;
                        if (b2 < PB) v1 = (float)(b2 - PB / 2) * (1.0f / 256.0f);
                    }
                    float out = v + fr * (v1 - v);
                    if (rsel) g_hi[ch] = out; else g_lo[ch] = out;
                    break;
                }
                cum += c;
            }
        }
    }
    __syncthreads();
    #pragma unroll
    for (int j = 0; j < PB / 1024; j++) h[tid * (PB / 1024) + j] = 0u;
}

// ---------------------------------------------------------------------------
// launch #6: normalize + mask
// ---------------------------------------------------------------------------
__global__ __launch_bounds__(512)
void final_kernel(const float* __restrict__ mask, float* __restrict__ out) {
    const int ch = blockIdx.y;
    const int nb = ch / 3;
    const int i = blockIdx.x * blockDim.x + threadIdx.x;
    const float lo = g_lo[ch], hi = g_hi[ch];
    const float inv = 1.0f / (hi - lo);
    float4 r = ((const float4*)(g_res + (size_t)ch * HW))[i];
    float4 m = ((const float4*)(mask + (size_t)nb * HW))[i];
    float4 o;
    o.x = (r.x - lo) * inv * m.x;
    o.y = (r.y - lo) * inv * m.y;
    o.z = (r.z - lo) * inv * m.z;
    o.w = (r.w - lo) * inv * m.w;
    ((float4*)out)[(size_t)ch * (HW / 4) + i] = o;
}

// ---------------------------------------------------------------------------
extern "C" void kernel_launch(void* const* d_in, const int* in_sizes, int n_in,
                              void* d_out, int out_size) {
    const float* x    = (const float*)d_in[0];
    const float* mask = (const float*)d_in[1];
    const float* kern = (const float*)d_in[2];
    float* out = (float*)d_out;

    cudaFuncSetAttribute(vconv, cudaFuncAttributeMaxDynamicSharedMemorySize, VCONV_SMEM);

    med_count<<<NCH * SEG, 512>>>(x, kern);
    med_sel<<<NCH, 1024>>>(x);
    hconv<<<dim3(W / HROWS, NCH), 256>>>(x, mask);
    vconv<<<dim3(W / VTX, W / VTY, NCH), 512, VCONV_SMEM>>>();
    pct_scan<<<NCH, 1024>>>();
    final_kernel<<<dim3(HW / 4 / 512, NCH), 512>>>(mask, out);
}

// round 17
// speedup vs baseline: 1.2723x; 1.0099x over previous
#include <cuda_runtime.h>
#include <cfloat>

#define HW   (512*512)
#define W    512
#define NCH  48            // 16 batches * 3 channels
#define FW   23
#define PAD  11

#define PB   8192          // pct histogram bins: i=(int)(res*256)+4096, res in (-16,16)
#define CAP  16384         // median candidate capacity per channel
#define SEG  8             // data-pass blocks per channel
// median fast-path candidate window in value space: [-10/512, +10/512)
#define T_LO (-10.0f/512.0f)
#define T_HI ( 10.0f/512.0f)

// hconv: 4 full rows per block, 256 threads (1 rotating group of 8 per thread)
#define HROWS 4
#define HROWW (W + 2*PAD)          // 534
// vconv: 64x128 output tile, 512 threads (2 rotating groups of 8 per thread)
#define VTX 64
#define VTY 128
#define VSH (VTY + 2*PAD)          // 150 rows of g_tmp
#define VCONV_SMEM ((VSH*VTX + PB/2) * 4)   // 37.5 KB tile + 16 KB packed hist

// scratch (no cudaMalloc allowed; zero-initialized at load, kernels restore zeros)
// g_res lifecycle per run: hconv writes xp -> vconv reads xp / overwrites res
// (same address, per-element read-before-write) -> final reads res.
__device__ float    g_res[(size_t)NCH * HW];
__device__ float    g_tmp[(size_t)NCH * HW];
__device__ unsigned g_phist[NCH * PB];
__device__ float    g_cand[NCH * CAP];
__device__ int      g_ccount[NCH];
__device__ int      g_below[NCH];
__device__ float    g_med[NCH];
__device__ float    g_lo[NCH];
__device__ float    g_hi[NCH];
__device__ float    g_k1[FW];

// ---------------------------------------------------------------------------
// block-wide exclusive scan over 1024 threads (shuffle-based)
// ---------------------------------------------------------------------------
__device__ __forceinline__ unsigned block_excl_scan_1024(unsigned val) {
    __shared__ unsigned warpsum[32];
    const unsigned lane = threadIdx.x & 31, wid = threadIdx.x >> 5;
    unsigned s = val;
    #pragma unroll
    for (int o = 1; o < 32; o <<= 1) {
        unsigned t = __shfl_up_sync(0xFFFFFFFFu, s, o);
        if (lane >= o) s += t;
    }
    if (lane == 31) warpsum[wid] = s;
    __syncthreads();
    if (wid == 0) {
        unsigned w = warpsum[lane];
        #pragma unroll
        for (int o = 1; o < 32; o <<= 1) {
            unsigned t = __shfl_up_sync(0xFFFFFFFFu, w, o);
            if (lane >= o) w += t;
        }
        warpsum[lane] = w;
    }
    __syncthreads();
    unsigned wexcl = wid ? warpsum[wid - 1] : 0u;
    return wexcl + s - val;
}

__device__ __forceinline__ int med_bin(float v) {   // for fallback only
    int b = (int)floorf(fmaf(v, 512.0f, 4096.0f));
    return b < 0 ? 0 : (b > 8191 ? 8191 : b);
}

// ---------------------------------------------------------------------------
// launch #1: count values below window + collect window candidates + k1 prep
// ---------------------------------------------------------------------------
__global__ __launch_bounds__(512)
void med_count(const float* __restrict__ x, const float* __restrict__ kern) {
    const int ch = blockIdx.x / SEG, seg = blockIdx.x % SEG;
    const int tid = threadIdx.x;
    if (blockIdx.x == 0 && tid < FW) {
        float s = 0.0f;
        for (int j = 0; j < FW; j++) s += kern[tid * FW + j];
        g_k1[tid] = s;
    }
    const float4* p = (const float4*)(x + (size_t)ch * HW) + (size_t)seg * (HW / 4 / SEG);
    int below = 0;
    for (int i = tid; i < HW / 4 / SEG; i += 512) {
        float4 v = p[i];
        float vv[4] = { v.x, v.y, v.z, v.w };
        #pragma unroll
        for (int j = 0; j < 4; j++) {
            float f = vv[j];
            below += (f < T_LO);
            if (f >= T_LO && f < T_HI) {
                int pp = atomicAdd(&g_ccount[ch], 1);
                if (pp < CAP) g_cand[ch * CAP + pp] = f;
            }
        }
    }
    for (int o = 16; o; o >>= 1) below += __shfl_down_sync(0xFFFFFFFFu, below, o);
    if ((tid & 31) == 0 && below) atomicAdd(&g_below[ch], below);
}

// ---------------------------------------------------------------------------
// launch #2: exact median selection (fast path via window; exact fallback)
// ---------------------------------------------------------------------------
__global__ __launch_bounds__(1024)
void med_sel(const float* __restrict__ x) {
    const int ch = blockIdx.x, tid = threadIdx.x;
    __shared__ unsigned fh[8192];
    __shared__ float s_red[32];
    __shared__ float s_mn, s_mx;
    __shared__ int s_fb, s_r2, s_n, s_k2;
    __shared__ int s_cnt;
    __shared__ float mem[512];
    __shared__ int mcount;

    const int k = (HW - 1) / 2;
    int below = g_below[ch];
    int cnt   = g_ccount[ch];
    __syncthreads();
    if (tid == 0) {
        g_below[ch] = 0;
        g_ccount[ch] = 0;
        s_cnt = 0;
    }
    const bool fast = (below <= k) && (k < below + cnt) && (cnt <= CAP);

    if (fast) {
        if (tid == 0) { s_n = cnt; s_k2 = k - below; }
        __syncthreads();
    } else {
        for (int i = tid; i < 8192; i += 1024) fh[i] = 0;
        __syncthreads();
        const float4* p = (const float4*)(x + (size_t)ch * HW);
        for (int i = tid; i < HW / 4; i += 1024) {
            float4 v = p[i];
            atomicAdd(&fh[med_bin(v.x)], 1u);
            atomicAdd(&fh[med_bin(v.y)], 1u);
            atomicAdd(&fh[med_bin(v.z)], 1u);
            atomicAdd(&fh[med_bin(v.w)], 1u);
        }
        __syncthreads();
        unsigned loc[8];
        unsigned s = 0;
        #pragma unroll
        for (int j = 0; j < 8; j++) { loc[j] = fh[tid * 8 + j]; s += loc[j]; }
        unsigned pref = block_excl_scan_1024(s);
        __shared__ int s_selbin;
        if (pref <= (unsigned)k && (unsigned)k < pref + s) {
            unsigned cum = pref;
            #pragma unroll
            for (int j = 0; j < 8; j++) {
                unsigned c = loc[j];
                if (cum + c > (unsigned)k) { s_selbin = tid * 8 + j; s_k2 = (int)(k - cum); break; }
                cum += c;
            }
        }
        __syncthreads();
        const int sb = s_selbin;
        for (int i = tid; i < HW / 4; i += 1024) {
            float4 v = p[i];
            float vv[4] = { v.x, v.y, v.z, v.w };
            #pragma unroll
            for (int j = 0; j < 4; j++) {
                if (med_bin(vv[j]) == sb) {
                    int pp = atomicAdd(&s_cnt, 1);
                    if (pp < CAP) g_cand[ch * CAP + pp] = vv[j];
                }
            }
        }
        __syncthreads();
        if (tid == 0) s_n = s_cnt < CAP ? s_cnt : CAP;
        __syncthreads();
    }

    const int n = s_n, k2 = s_k2;
    const float* c = g_cand + ch * CAP;

    float mn = FLT_MAX, mx = -FLT_MAX;
    for (int i = tid; i < n; i += 1024) {
        float v = c[i];
        mn = fminf(mn, v); mx = fmaxf(mx, v);
    }
    for (int o = 16; o; o >>= 1) {
        mn = fminf(mn, __shfl_down_sync(0xFFFFFFFFu, mn, o));
        mx = fmaxf(mx, __shfl_down_sync(0xFFFFFFFFu, mx, o));
    }
    if ((tid & 31) == 0) s_red[tid >> 5] = mn;
    __syncthreads();
    if (tid < 32) {
        float v = s_red[tid];
        for (int o = 16; o; o >>= 1) v = fminf(v, __shfl_down_sync(0xFFFFFFFFu, v, o));
        if (tid == 0) s_mn = v;
    }
    __syncthreads();
    if ((tid & 31) == 0) s_red[tid >> 5] = mx;
    __syncthreads();
    if (tid < 32) {
        float v = s_red[tid];
        for (int o = 16; o; o >>= 1) v = fmaxf(v, __shfl_down_sync(0xFFFFFFFFu, v, o));
        if (tid == 0) s_mx = v;
    }
    __syncthreads();
    const float mnv = s_mn, mxv = s_mx;
    if (mnv == mxv) { if (tid == 0) g_med[ch] = mnv + 0.2f; return; }

    for (int i = tid; i < 8192; i += 1024) fh[i] = 0;
    __syncthreads();
    const float scale = 8192.0f / (mxv - mnv);
    for (int i = tid; i < n; i += 1024) {
        int b = (int)((c[i] - mnv) * scale);
        b = b < 0 ? 0 : (b > 8191 ? 8191 : b);
        atomicAdd(&fh[b], 1u);
    }
    __syncthreads();
    unsigned loc[8];
    unsigned s = 0;
    #pragma unroll
    for (int j = 0; j < 8; j++) { loc[j] = fh[tid * 8 + j]; s += loc[j]; }
    unsigned pref = block_excl_scan_1024(s);
    if (pref <= (unsigned)k2 && (unsigned)k2 < pref + s) {
        unsigned cum = pref;
        #pragma unroll
        for (int j = 0; j < 8; j++) {
            unsigned cc = loc[j];
            if (cum + cc > (unsigned)k2) { s_fb = tid * 8 + j; s_r2 = (int)(k2 - cum); break; }
            cum += cc;
        }
    }
    if (tid == 0) mcount = 0;
    __syncthreads();
    const int fb = s_fb, r2 = s_r2;
    for (int i = tid; i < n; i += 1024) {
        int b = (int)((c[i] - mnv) * scale);
        b = b < 0 ? 0 : (b > 8191 ? 8191 : b);
        if (b == fb) {
            int pp = atomicAdd(&mcount, 1);
            if (pp < 512) mem[pp] = c[i];
        }
    }
    __syncthreads();
    int m = mcount < 512 ? mcount : 512;
    for (int i = tid; i < m; i += 1024) {
        float vi = mem[i];
        int r = 0;
        for (int j = 0; j < m; j++) {
            float vj = mem[j];
            r += (vj < vi) || (vj == vi && j < i);
        }
        if (r == r2) g_med[ch] = vi + 0.2f;
    }
}

// ---------------------------------------------------------------------------
// launch #3: horizontal conv — 4 full rows/block, xp fused; rotating window
// (no register shifts). Writes h-conv to g_tmp AND xp to g_res.
// ---------------------------------------------------------------------------
__global__ __launch_bounds__(256)
void hconv(const float* __restrict__ x, const float* __restrict__ mask) {
    __shared__ float xp[HROWS][HROWW];                // 4 x 534 floats = 8.5 KB
    __shared__ float s_k[FW];
    const int tid = threadIdx.x;
    const int ch = blockIdx.y;
    const int nb = ch / 3;
    const int row0 = blockIdx.x * HROWS;

    if (tid < FW) s_k[tid] = g_k1[tid];

    const float* xc = x + (size_t)ch * HW;
    const float* mc = mask + (size_t)nb * HW;
    const float med = g_med[ch];

    #pragma unroll
    for (int r = 0; r < HROWS; r++) {
        const float* xr = xc + (size_t)(row0 + r) * W;
        const float* mr = mc + (size_t)(row0 + r) * W;
        for (int cc = tid; cc < HROWW; cc += 256) {
            int gc = min(max(cc - PAD, 0), W - 1);
            float xv = xr[gc];
            float mv = mr[gc];
            xp[r][cc] = mv * xv + (1.0f - mv) * med;
        }
    }
    __syncthreads();

    // rotating 10-slot window (mod-10 compile-time indices), float2 refills
    const int r = tid >> 6, g = tid & 63;
    const float* rowp = xp[r] + g * 8;
    float w[10], acc[8];
    #pragma unroll
    for (int i = 0; i < 5; i++) {
        float2 v = *(const float2*)(rowp + 2 * i);
        w[2 * i] = v.x; w[2 * i + 1] = v.y;
    }
    #pragma unroll
    for (int m = 0; m < 8; m++) acc[m] = 0.0f;
    #pragma unroll
    for (int tp = 0; tp < 11; tp++) {                 // taps 2tp, 2tp+1 (0..21)
        const float k0 = s_k[2 * tp], k1v = s_k[2 * tp + 1];
        #pragma unroll
        for (int m = 0; m < 8; m++) acc[m] = fmaf(w[(2 * tp + m) % 10], k0, acc[m]);
        #pragma unroll
        for (int m = 0; m < 8; m++) acc[m] = fmaf(w[(2 * tp + 1 + m) % 10], k1v, acc[m]);
        if (tp < 10) {                                // refill dead slots
            float2 v = *(const float2*)(rowp + 2 * tp + 10);
            w[(2 * tp) % 10] = v.x;
            w[(2 * tp + 1) % 10] = v.y;
        }
    }
    const float k22 = s_k[22];                        // tap 22: v[22+m] at slot (22+m)%10
    #pragma unroll
    for (int m = 0; m < 8; m++) acc[m] = fmaf(w[(22 + m) % 10], k22, acc[m]);

    const size_t base = (size_t)ch * HW + (size_t)(row0 + r) * W + g * 8;
    float4* outp = (float4*)(g_tmp + base);
    outp[0] = make_float4(acc[0], acc[1], acc[2], acc[3]);
    outp[1] = make_float4(acc[4], acc[5], acc[6], acc[7]);

    // stash xp (central values) for vconv: xp at out col c is xp[r][c+PAD]
    float4* xpo = (float4*)(g_res + base);
    const float* xs = xp[r] + g * 8 + PAD;
    xpo[0] = make_float4(xs[0], xs[1], xs[2], xs[3]);
    xpo[1] = make_float4(xs[4], xs[5], xs[6], xs[7]);
}

// ---------------------------------------------------------------------------
// launch #4: vertical conv + res (in place over xp) + fused packed-u16 pct hist
// 64x128 tile, 512 threads, 2 rotating groups of 8 per thread (no shifts)
// ---------------------------------------------------------------------------
__global__ __launch_bounds__(512)
void vconv() {
    extern __shared__ float dsm[];
    float*    st  = dsm;                              // VSH x VTX g_tmp tile
    unsigned* s_h = (unsigned*)(dsm + VSH * VTX);     // PB/2 packed hist
    __shared__ float s_k[FW];

    const int tid = threadIdx.x;
    const int ch = blockIdx.z;
    const int bx = blockIdx.x * VTX, by = blockIdx.y * VTY;

    if (tid < FW) s_k[tid] = g_k1[tid];
    for (int i = tid; i < PB / 2; i += 512) s_h[i] = 0;

    const float* tc = g_tmp + (size_t)ch * HW;
    for (int i = tid; i < VSH * VTX; i += 512) {
        int r = i >> 6, c = i & 63;
        int gy = min(max(by - PAD + r, 0), 511);
        st[r * VTX + c] = tc[gy * W + bx + c];
    }
    __syncthreads();

    const int xx = tid & 63;
    const int ybase = (tid >> 6) * 16;                // 8 slots of 16 rows
    #pragma unroll
    for (int g2 = 0; g2 < 2; g2++) {
        const int y0 = ybase + g2 * 8;
        const float* col = st + y0 * VTX + xx;
        float w[8], acc[8];
        #pragma unroll
        for (int m = 0; m < 8; m++) { w[m] = col[m * VTX]; acc[m] = 0.0f; }
        #pragma unroll
        for (int t = 0; t < FW; t++) {                // rotating mod-8 window
            const float kt = s_k[t];
            #pragma unroll
            for (int m = 0; m < 8; m++) acc[m] = fmaf(w[(t + m) & 7], kt, acc[m]);
            if (t < FW - 1) w[t & 7] = col[(t + 8) * VTX];
        }

        // read xp (stored by hconv) and overwrite with res, same address
        float* rp = g_res + (size_t)ch * HW + (size_t)(by + y0) * W + bx + xx;
        #pragma unroll
        for (int m = 0; m < 8; m++) {
            float xpv = rp[m * W];
            float rv = 4.0f * (xpv - acc[m]);
            rp[m * W] = rv;
            int b = (int)(rv * 256.0f) + PB / 2;
            b = b < 0 ? 0 : (b > PB - 1 ? PB - 1 : b);
            atomicAdd(&s_h[b >> 1], 1u << ((b & 1) * 16));
        }
    }
    __syncthreads();

    unsigned* gh = g_phist + ch * PB;
    for (int i = tid; i < PB / 2; i += 512) {
        unsigned w2 = s_h[i];
        unsigned lo = w2 & 0xFFFFu, hi = w2 >> 16;
        if (lo) atomicAdd(&gh[2 * i], lo);
        if (hi) atomicAdd(&gh[2 * i + 1], hi);
    }
}

// ---------------------------------------------------------------------------
// launch #5: extract lo/hi percentiles, restore hist to zero
// ---------------------------------------------------------------------------
__global__ __launch_bounds__(1024)
void pct_scan() {
    const int ch = blockIdx.x, tid = threadIdx.x;
    unsigned* h = g_phist + ch * PB;
    unsigned loc[PB / 1024];
    unsigned s = 0;
    #pragma unroll
    for (int j = 0; j < PB / 1024; j++) { loc[j] = h[tid * (PB / 1024) + j]; s += loc[j]; }
    unsigned pref = block_excl_scan_1024(s);

    const double n1 = (double)(HW - 1);
    #pragma unroll
    for (int rsel = 0; rsel < 2; rsel++) {
        double pos = n1 * (rsel ? 0.97 : 0.03);
        unsigned k = (unsigned)pos;
        float fr = (float)(pos - (double)k);
        if (pref <= k && k < pref + s) {
            unsigned cum = pref;
            #pragma unroll
            for (int j = 0; j < PB / 1024; j++) {
                unsigned c = loc[j];
                int b = tid * (PB / 1024) + j;
                if (cum + c > k) {
                    float v = (float)(b - PB / 2) * (1.0f / 256.0f);
                    float v1 = v;
                    if (k + 1 >= cum + c) {
                        int b2 = b + 1;
                        while (b2 < PB && h[b2] == 0) b2++;
                        if (b2 < PB) v1 = (float)(b2 - PB / 2) * (1.0f / 256.0f);
                    }
                    float out = v + fr * (v1 - v);
                    if (rsel) g_hi[ch] = out; else g_lo[ch] = out;
                    break;
                }
                cum += c;
            }
        }
    }
    __syncthreads();
    #pragma unroll
    for (int j = 0; j < PB / 1024; j++) h[tid * (PB / 1024) + j] = 0u;
}

// ---------------------------------------------------------------------------
// launch #6: normalize + mask
// ---------------------------------------------------------------------------
__global__ __launch_bounds__(512)
void final_kernel(const float* __restrict__ mask, float* __restrict__ out) {
    const int ch = blockIdx.y;
    const int nb = ch / 3;
    const int i = blockIdx.x * blockDim.x + threadIdx.x;
    const float lo = g_lo[ch], hi = g_hi[ch];
    const float inv = 1.0f / (hi - lo);
    float4 r = ((const float4*)(g_res + (size_t)ch * HW))[i];
    float4 m = ((const float4*)(mask + (size_t)nb * HW))[i];
    float4 o;
    o.x = (r.x - lo) * inv * m.x;
    o.y = (r.y - lo) * inv * m.y;
    o.z = (r.z - lo) * inv * m.z;
    o.w = (r.w - lo) * inv * m.w;
    ((float4*)out)[(size_t)ch * (HW / 4) + i] = o;
}

// ---------------------------------------------------------------------------
extern "C" void kernel_launch(void* const* d_in, const int* in_sizes, int n_in,
                              void* d_out, int out_size) {
    const float* x    = (const float*)d_in[0];
    const float* mask = (const float*)d_in[1];
    const float* kern = (const float*)d_in[2];
    float* out = (float*)d_out;

    cudaFuncSetAttribute(vconv, cudaFuncAttributeMaxDynamicSharedMemorySize, VCONV_SMEM);

    med_count<<<NCH * SEG, 512>>>(x, kern);
    med_sel<<<NCH, 1024>>>(x);
    hconv<<<dim3(W / HROWS, NCH), 256>>>(x, mask);
    vconv<<<dim3(W / VTX, W / VTY, NCH), 512, VCONV_SMEM>>>();
    pct_scan<<<NCH, 1024>>>();
    final_kernel<<<dim3(HW / 4 / 512, NCH), 512>>>(mask, out);
}